// round 1
// baseline (speedup 1.0000x reference)
#include <cuda_runtime.h>
#include <math_constants.h>

// Problem constants (fixed by the reference)
namespace {
constexpr int B  = 4;
constexpr int S  = 2048;
constexpr int H  = 1024;
constexpr int NH = 16;
constexpr int HD = 64;
constexpr int MROWS = B * S;  // 8192
constexpr size_t OUT_ELEMS  = (size_t)B * S * H;          // 8,388,608
constexpr size_t ATTN_ELEMS = (size_t)B * NH * S * S;     // 268,435,456
}

// Scratch (allocation-free rule: __device__ globals)
__device__ float g_q[(size_t)B * NH * S * HD];
__device__ float g_k[(size_t)B * NH * S * HD];
__device__ float g_v[(size_t)B * NH * S * HD];
__device__ float g_ctx[(size_t)B * S * H];
__device__ float g_attn_fb[ATTN_ELEMS];   // fallback if d_out lacks attn space

// ---------------------------------------------------------------------------
// GEMM: C[M,N] = A[M,K] @ W[N,K]^T + bias[N]
// 128x128 tile, BK=16, 256 threads, 8x8 per thread.
// MODE 0: plain row-major C.
// MODE 1: projection output scatter to [B, NH, S, HD].
// ---------------------------------------------------------------------------
template <int MODE>
__global__ __launch_bounds__(256) void gemm_xwt_bias(
    const float* __restrict__ A, const float* __restrict__ W,
    const float* __restrict__ bias, float* __restrict__ C,
    int M, int N, int K)
{
    __shared__ __align__(16) float As[16][128];
    __shared__ __align__(16) float Ws[16][128];

    const int tid  = threadIdx.x;
    const int row0 = blockIdx.y * 128;
    const int col0 = blockIdx.x * 128;
    const int tm = tid >> 4;         // 0..15
    const int tn = tid & 15;         // 0..15
    const int lr = tid >> 2;         // 0..63
    const int lk = (tid & 3) << 2;   // 0,4,8,12

    float acc[8][8] = {};

    for (int k0 = 0; k0 < K; k0 += 16) {
#pragma unroll
        for (int hh = 0; hh < 2; hh++) {
            int r = lr + hh * 64;
            float4 va = *reinterpret_cast<const float4*>(
                A + (size_t)(row0 + r) * K + k0 + lk);
            As[lk + 0][r] = va.x; As[lk + 1][r] = va.y;
            As[lk + 2][r] = va.z; As[lk + 3][r] = va.w;
            float4 vw = *reinterpret_cast<const float4*>(
                W + (size_t)(col0 + r) * K + k0 + lk);
            Ws[lk + 0][r] = vw.x; Ws[lk + 1][r] = vw.y;
            Ws[lk + 2][r] = vw.z; Ws[lk + 3][r] = vw.w;
        }
        __syncthreads();
#pragma unroll
        for (int k = 0; k < 16; k++) {
            float4 a0 = *reinterpret_cast<const float4*>(&As[k][tm * 8]);
            float4 a1 = *reinterpret_cast<const float4*>(&As[k][tm * 8 + 4]);
            float4 b0 = *reinterpret_cast<const float4*>(&Ws[k][tn * 8]);
            float4 b1 = *reinterpret_cast<const float4*>(&Ws[k][tn * 8 + 4]);
            float a[8] = {a0.x, a0.y, a0.z, a0.w, a1.x, a1.y, a1.z, a1.w};
            float b[8] = {b0.x, b0.y, b0.z, b0.w, b1.x, b1.y, b1.z, b1.w};
#pragma unroll
            for (int i = 0; i < 8; i++)
#pragma unroll
                for (int j = 0; j < 8; j++)
                    acc[i][j] = fmaf(a[i], b[j], acc[i][j]);
        }
        __syncthreads();
    }

#pragma unroll
    for (int i = 0; i < 8; i++) {
        int m = row0 + tm * 8 + i;
#pragma unroll
        for (int j = 0; j < 8; j++) {
            int n = col0 + tn * 8 + j;
            float val = acc[i][j] + bias[n];
            if (MODE == 0) {
                C[(size_t)m * N + n] = val;
            } else {
                int bb = m / S, ss = m % S;
                int hh = n / HD, dd = n % HD;
                C[(((size_t)bb * NH + hh) * S + ss) * HD + dd] = val;
            }
        }
    }
}

// ---------------------------------------------------------------------------
// Scores: per (b,h): scores[i,j] = (q[i,:] . k[j,:]) / 8, causal mask -> -inf
// 128x128 tile over [S,S], K=HD=64. Fully-masked tiles skip compute.
// ---------------------------------------------------------------------------
__global__ __launch_bounds__(256) void scores_kernel(
    const float* __restrict__ Qp, const float* __restrict__ Kp,
    float* __restrict__ attn, const int* __restrict__ causal_p)
{
    const int z    = blockIdx.z;               // b*NH + h
    const int row0 = blockIdx.y * 128;
    const int col0 = blockIdx.x * 128;
    const int tid  = threadIdx.x;
    const int tm = tid >> 4, tn = tid & 15;
    const int causal = *causal_p;
    float* out = attn + (size_t)z * S * S;
    const float NEG = -CUDART_INF_F;

    if (causal && col0 >= row0 + 128) {
        // fully above the diagonal: just write -inf
#pragma unroll
        for (int i = 0; i < 8; i++) {
            size_t rbase = (size_t)(row0 + tm * 8 + i) * S + col0 + tn * 8;
#pragma unroll
            for (int j = 0; j < 8; j++) out[rbase + j] = NEG;
        }
        return;
    }

    const float* Aq = Qp + (size_t)z * S * HD;
    const float* Bk = Kp + (size_t)z * S * HD;

    __shared__ __align__(16) float As[16][128];
    __shared__ __align__(16) float Ws[16][128];
    const int lr = tid >> 2, lk = (tid & 3) << 2;

    float acc[8][8] = {};
#pragma unroll
    for (int k0 = 0; k0 < HD; k0 += 16) {
#pragma unroll
        for (int hh = 0; hh < 2; hh++) {
            int r = lr + hh * 64;
            float4 va = *reinterpret_cast<const float4*>(
                Aq + (size_t)(row0 + r) * HD + k0 + lk);
            As[lk + 0][r] = va.x; As[lk + 1][r] = va.y;
            As[lk + 2][r] = va.z; As[lk + 3][r] = va.w;
            float4 vw = *reinterpret_cast<const float4*>(
                Bk + (size_t)(col0 + r) * HD + k0 + lk);
            Ws[lk + 0][r] = vw.x; Ws[lk + 1][r] = vw.y;
            Ws[lk + 2][r] = vw.z; Ws[lk + 3][r] = vw.w;
        }
        __syncthreads();
#pragma unroll
        for (int k = 0; k < 16; k++) {
            float4 a0 = *reinterpret_cast<const float4*>(&As[k][tm * 8]);
            float4 a1 = *reinterpret_cast<const float4*>(&As[k][tm * 8 + 4]);
            float4 b0 = *reinterpret_cast<const float4*>(&Ws[k][tn * 8]);
            float4 b1 = *reinterpret_cast<const float4*>(&Ws[k][tn * 8 + 4]);
            float a[8] = {a0.x, a0.y, a0.z, a0.w, a1.x, a1.y, a1.z, a1.w};
            float b[8] = {b0.x, b0.y, b0.z, b0.w, b1.x, b1.y, b1.z, b1.w};
#pragma unroll
            for (int i = 0; i < 8; i++)
#pragma unroll
                for (int j = 0; j < 8; j++)
                    acc[i][j] = fmaf(a[i], b[j], acc[i][j]);
        }
        __syncthreads();
    }

#pragma unroll
    for (int i = 0; i < 8; i++) {
        int m = row0 + tm * 8 + i;
#pragma unroll
        for (int j = 0; j < 8; j++) {
            int n = col0 + tn * 8 + j;
            float val = acc[i][j] * 0.125f;   // 1/sqrt(64)
            if (causal && n > m) val = NEG;
            out[(size_t)m * S + n] = val;
        }
    }
}

// ---------------------------------------------------------------------------
// Row softmax, in place. One block per row (S=2048 cols, 256 threads x 8).
// ---------------------------------------------------------------------------
__global__ __launch_bounds__(256) void softmax_kernel(float* __restrict__ attn)
{
    float* p = attn + (size_t)blockIdx.x * S;
    const int t = threadIdx.x;
    float x[8];
#pragma unroll
    for (int i = 0; i < 8; i++) x[i] = p[t + 256 * i];

    float m = x[0];
#pragma unroll
    for (int i = 1; i < 8; i++) m = fmaxf(m, x[i]);
#pragma unroll
    for (int o = 16; o > 0; o >>= 1)
        m = fmaxf(m, __shfl_xor_sync(0xffffffffu, m, o));

    __shared__ float red[8];
    if ((t & 31) == 0) red[t >> 5] = m;
    __syncthreads();
    float bm = red[0];
#pragma unroll
    for (int i = 1; i < 8; i++) bm = fmaxf(bm, red[i]);

    float ssum = 0.f;
#pragma unroll
    for (int i = 0; i < 8; i++) { x[i] = __expf(x[i] - bm); ssum += x[i]; }
#pragma unroll
    for (int o = 16; o > 0; o >>= 1)
        ssum += __shfl_xor_sync(0xffffffffu, ssum, o);
    __syncthreads();
    if ((t & 31) == 0) red[t >> 5] = ssum;
    __syncthreads();
    float tot = 0.f;
#pragma unroll
    for (int i = 0; i < 8; i++) tot += red[i];

    float inv = 1.0f / tot;
#pragma unroll
    for (int i = 0; i < 8; i++) p[t + 256 * i] = x[i] * inv;
}

// ---------------------------------------------------------------------------
// Context: per (b,h): ctx[i,d] = sum_j attn[i,j] * v[j,d]
// 64x64 tile (N=HD=64), BK=16, 256 threads, 4x4 per thread.
// Causal: attn[i,j]=0 for j>i, so K-loop stops at row0+64.
// Output written directly in [B, S, H] (head-merged) layout.
// ---------------------------------------------------------------------------
__global__ __launch_bounds__(256) void context_kernel(
    const float* __restrict__ attn, const float* __restrict__ Vp,
    float* __restrict__ ctx, const int* __restrict__ causal_p)
{
    const int z    = blockIdx.z;
    const int row0 = blockIdx.y * 64;
    const int causal = *causal_p;
    const float* Aa = attn + (size_t)z * S * S;
    const float* Vv = Vp + (size_t)z * S * HD;

    __shared__ __align__(16) float As[16][64];
    __shared__ __align__(16) float Vs[16][64];

    const int tid = threadIdx.x;
    const int tm = tid >> 4, tn = tid & 15;
    const int ar = tid >> 2, ak = (tid & 3) << 2;   // A tile: 64 rows x 16 k
    const int vr = tid >> 4, vc = (tid & 15) << 2;  // V tile: 16 rows x 64 d

    float acc[4][4] = {};
    const int jend = causal ? (row0 + 64) : S;

    for (int j0 = 0; j0 < jend; j0 += 16) {
        float4 av = *reinterpret_cast<const float4*>(
            Aa + (size_t)(row0 + ar) * S + j0 + ak);
        As[ak + 0][ar] = av.x; As[ak + 1][ar] = av.y;
        As[ak + 2][ar] = av.z; As[ak + 3][ar] = av.w;
        *reinterpret_cast<float4*>(&Vs[vr][vc]) =
            *reinterpret_cast<const float4*>(Vv + (size_t)(j0 + vr) * HD + vc);
        __syncthreads();
#pragma unroll
        for (int k = 0; k < 16; k++) {
            float4 a4 = *reinterpret_cast<const float4*>(&As[k][tm * 4]);
            float4 v4 = *reinterpret_cast<const float4*>(&Vs[k][tn * 4]);
            float a[4] = {a4.x, a4.y, a4.z, a4.w};
            float v[4] = {v4.x, v4.y, v4.z, v4.w};
#pragma unroll
            for (int i = 0; i < 4; i++)
#pragma unroll
                for (int j = 0; j < 4; j++)
                    acc[i][j] = fmaf(a[i], v[j], acc[i][j]);
        }
        __syncthreads();
    }

    const int bb = z / NH, hh = z % NH;
#pragma unroll
    for (int i = 0; i < 4; i++) {
        int srow = row0 + tm * 4 + i;
        size_t base = ((size_t)bb * S + srow) * H + hh * HD + tn * 4;
#pragma unroll
        for (int j = 0; j < 4; j++) ctx[base + j] = acc[i][j];
    }
}

// ---------------------------------------------------------------------------
// Launch
// ---------------------------------------------------------------------------
extern "C" void kernel_launch(void* const* d_in, const int* in_sizes, int n_in,
                              void* d_out, int out_size)
{
    const float* query = (const float*)d_in[0];
    const float* key_   = (const float*)d_in[1];
    const float* value = (const float*)d_in[2];
    const float* Wq = (const float*)d_in[3];
    const float* bq = (const float*)d_in[4];
    const float* Wk = (const float*)d_in[5];
    const float* bk = (const float*)d_in[6];
    const float* Wv = (const float*)d_in[7];
    const float* bv = (const float*)d_in[8];
    const float* Wo = (const float*)d_in[9];
    const float* bo = (const float*)d_in[10];
    const int* causal = (const int*)d_in[11];

    float *qp, *kp, *vp, *cp, *afb;
    cudaGetSymbolAddress((void**)&qp, g_q);
    cudaGetSymbolAddress((void**)&kp, g_k);
    cudaGetSymbolAddress((void**)&vp, g_v);
    cudaGetSymbolAddress((void**)&cp, g_ctx);
    cudaGetSymbolAddress((void**)&afb, g_attn_fb);

    float* out = (float*)d_out;
    // Output layout: [output (B*S*H) | attn_weights (B*NH*S*S)] when both fit.
    float* attn = ((size_t)out_size >= OUT_ELEMS + ATTN_ELEMS) ? (out + OUT_ELEMS)
                                                               : afb;

    dim3 gproj(H / 128, MROWS / 128);                 // (8, 64)
    gemm_xwt_bias<1><<<gproj, 256>>>(query, Wq, bq, qp, MROWS, H, H);
    gemm_xwt_bias<1><<<gproj, 256>>>(key_,  Wk, bk, kp, MROWS, H, H);
    gemm_xwt_bias<1><<<gproj, 256>>>(value, Wv, bv, vp, MROWS, H, H);

    dim3 gsc(S / 128, S / 128, B * NH);               // (16, 16, 64)
    scores_kernel<<<gsc, 256>>>(qp, kp, attn, causal);

    softmax_kernel<<<B * NH * S, 256>>>(attn);        // 131072 rows

    dim3 gctx(1, S / 64, B * NH);                     // (1, 32, 64)
    context_kernel<<<gctx, 256>>>(attn, vp, cp, causal);

    gemm_xwt_bias<0><<<gproj, 256>>>(cp, Wo, bo, out, MROWS, H, H);
}

// round 2
// speedup vs baseline: 2.3253x; 2.3253x over previous
#include <cuda_runtime.h>
#include <math_constants.h>
#include <cstdint>

namespace {
constexpr int B  = 4;
constexpr int S  = 2048;
constexpr int H  = 1024;
constexpr int NH = 16;
constexpr int HD = 64;
constexpr int MROWS = B * S;  // 8192
constexpr size_t OUT_ELEMS  = (size_t)B * S * H;
constexpr size_t ATTN_ELEMS = (size_t)B * NH * S * S;
constexpr int ASTR = 136;  // 128 + 8 pad -> conflict-free fragment loads
constexpr int VSTR = 72;   // 64 + 8 pad
}

// Scratch (allocation-free rule: __device__ globals)
__device__ float g_q[(size_t)B * NH * S * HD];
__device__ float g_k[(size_t)B * NH * S * HD];
__device__ float g_v[(size_t)B * NH * S * HD];
__device__ float g_ctx[(size_t)B * S * H];
__device__ float g_attn_fb[ATTN_ELEMS];

// ---------------------------------------------------------------------------
// tf32 helpers
// ---------------------------------------------------------------------------
__device__ __forceinline__ uint32_t tf32_of(float x) {
    uint32_t y;
    asm("cvt.rna.tf32.f32 %0, %1;" : "=r"(y) : "f"(x));
    return y;
}

__device__ __forceinline__ void mma8(float c[4],
                                     uint32_t a0, uint32_t a1, uint32_t a2, uint32_t a3,
                                     uint32_t b0, uint32_t b1) {
    asm volatile(
        "mma.sync.aligned.m16n8k8.row.col.f32.tf32.tf32.f32 "
        "{%0,%1,%2,%3}, {%4,%5,%6,%7}, {%8,%9}, {%0,%1,%2,%3};"
        : "+f"(c[0]), "+f"(c[1]), "+f"(c[2]), "+f"(c[3])
        : "r"(a0), "r"(a1), "r"(a2), "r"(a3), "r"(b0), "r"(b1));
}

// ---------------------------------------------------------------------------
// GEMM: C[M,N] = A[M,K] @ W[N,K]^T + bias[N]   (tf32 tensor cores)
// Block 128x128, BK=16, 256 threads = 8 warps (2m x 4n), warp tile 64x32.
// MODE 0: row-major C.  MODE 1: scatter to [B, NH, S, HD].
// ---------------------------------------------------------------------------
template <int MODE>
__global__ __launch_bounds__(256) void gemm_tf32(
    const float* __restrict__ A, const float* __restrict__ W,
    const float* __restrict__ bias, float* __restrict__ C,
    int M, int N, int K)
{
    __shared__ uint32_t As[16][ASTR];
    __shared__ uint32_t Ws[16][ASTR];

    const int tid  = threadIdx.x;
    const int lane = tid & 31, wid = tid >> 5;
    const int row0 = blockIdx.y * 128, col0 = blockIdx.x * 128;
    const int wm = (wid >> 2) * 64, wn = (wid & 3) * 32;
    const int g = lane >> 2, tig = lane & 3;
    const int lr = tid >> 2, lk = (tid & 3) << 2;

    float acc[4][4][4] = {};

    for (int k0 = 0; k0 < K; k0 += 16) {
#pragma unroll
        for (int hh = 0; hh < 2; hh++) {
            int r = lr + hh * 64;
            float4 va = *reinterpret_cast<const float4*>(
                A + (size_t)(row0 + r) * K + k0 + lk);
            As[lk + 0][r] = tf32_of(va.x); As[lk + 1][r] = tf32_of(va.y);
            As[lk + 2][r] = tf32_of(va.z); As[lk + 3][r] = tf32_of(va.w);
            float4 vw = *reinterpret_cast<const float4*>(
                W + (size_t)(col0 + r) * K + k0 + lk);
            Ws[lk + 0][r] = tf32_of(vw.x); Ws[lk + 1][r] = tf32_of(vw.y);
            Ws[lk + 2][r] = tf32_of(vw.z); Ws[lk + 3][r] = tf32_of(vw.w);
        }
        __syncthreads();
#pragma unroll
        for (int kk = 0; kk < 16; kk += 8) {
            uint32_t a[4][4], b[4][2];
#pragma unroll
            for (int mt = 0; mt < 4; mt++) {
                int m = wm + mt * 16 + g;
                a[mt][0] = As[kk + tig][m];     a[mt][1] = As[kk + tig][m + 8];
                a[mt][2] = As[kk + tig + 4][m]; a[mt][3] = As[kk + tig + 4][m + 8];
            }
#pragma unroll
            for (int nt = 0; nt < 4; nt++) {
                int n = wn + nt * 8 + g;
                b[nt][0] = Ws[kk + tig][n];     b[nt][1] = Ws[kk + tig + 4][n];
            }
#pragma unroll
            for (int mt = 0; mt < 4; mt++)
#pragma unroll
                for (int nt = 0; nt < 4; nt++)
                    mma8(acc[mt][nt], a[mt][0], a[mt][1], a[mt][2], a[mt][3],
                         b[nt][0], b[nt][1]);
        }
        __syncthreads();
    }

#pragma unroll
    for (int mt = 0; mt < 4; mt++) {
#pragma unroll
        for (int rr = 0; rr < 2; rr++) {
            int m = row0 + wm + mt * 16 + g + rr * 8;
#pragma unroll
            for (int nt = 0; nt < 4; nt++) {
                int n = col0 + wn + nt * 8 + 2 * tig;
                float v0 = acc[mt][nt][rr * 2 + 0] + bias[n];
                float v1 = acc[mt][nt][rr * 2 + 1] + bias[n + 1];
                if (MODE == 0) {
                    *reinterpret_cast<float2*>(C + (size_t)m * N + n) =
                        make_float2(v0, v1);
                } else {
                    int bb = m / S, ss = m % S;
                    int hh2 = n / HD, dd = n % HD;
                    *reinterpret_cast<float2*>(
                        C + (((size_t)bb * NH + hh2) * S + ss) * HD + dd) =
                        make_float2(v0, v1);
                }
            }
        }
    }
}

// ---------------------------------------------------------------------------
// Scores: per (b,h): raw[i,j] = (q[i].k[j]) / 8 with causal -inf on diag tile.
// Fully-masked tiles are SKIPPED entirely (no write) — softmax synthesizes.
// ---------------------------------------------------------------------------
__global__ __launch_bounds__(256) void scores_tf32(
    const float* __restrict__ Qp, const float* __restrict__ Kp,
    float* __restrict__ attn, const int* __restrict__ causal_p)
{
    const int z    = blockIdx.z;
    const int row0 = blockIdx.y * 128, col0 = blockIdx.x * 128;
    const int causal = *causal_p;
    if (causal && col0 >= row0 + 128) return;  // fully masked: skip

    const float* Aq = Qp + (size_t)z * S * HD;
    const float* Bk = Kp + (size_t)z * S * HD;
    float* out = attn + (size_t)z * S * S;

    __shared__ uint32_t As[16][ASTR];
    __shared__ uint32_t Ws[16][ASTR];

    const int tid  = threadIdx.x;
    const int lane = tid & 31, wid = tid >> 5;
    const int wm = (wid >> 2) * 64, wn = (wid & 3) * 32;
    const int g = lane >> 2, tig = lane & 3;
    const int lr = tid >> 2, lk = (tid & 3) << 2;

    float acc[4][4][4] = {};

#pragma unroll
    for (int k0 = 0; k0 < HD; k0 += 16) {
#pragma unroll
        for (int hh = 0; hh < 2; hh++) {
            int r = lr + hh * 64;
            float4 va = *reinterpret_cast<const float4*>(
                Aq + (size_t)(row0 + r) * HD + k0 + lk);
            As[lk + 0][r] = tf32_of(va.x); As[lk + 1][r] = tf32_of(va.y);
            As[lk + 2][r] = tf32_of(va.z); As[lk + 3][r] = tf32_of(va.w);
            float4 vw = *reinterpret_cast<const float4*>(
                Bk + (size_t)(col0 + r) * HD + k0 + lk);
            Ws[lk + 0][r] = tf32_of(vw.x); Ws[lk + 1][r] = tf32_of(vw.y);
            Ws[lk + 2][r] = tf32_of(vw.z); Ws[lk + 3][r] = tf32_of(vw.w);
        }
        __syncthreads();
#pragma unroll
        for (int kk = 0; kk < 16; kk += 8) {
            uint32_t a[4][4], b[4][2];
#pragma unroll
            for (int mt = 0; mt < 4; mt++) {
                int m = wm + mt * 16 + g;
                a[mt][0] = As[kk + tig][m];     a[mt][1] = As[kk + tig][m + 8];
                a[mt][2] = As[kk + tig + 4][m]; a[mt][3] = As[kk + tig + 4][m + 8];
            }
#pragma unroll
            for (int nt = 0; nt < 4; nt++) {
                int n = wn + nt * 8 + g;
                b[nt][0] = Ws[kk + tig][n];     b[nt][1] = Ws[kk + tig + 4][n];
            }
#pragma unroll
            for (int mt = 0; mt < 4; mt++)
#pragma unroll
                for (int nt = 0; nt < 4; nt++)
                    mma8(acc[mt][nt], a[mt][0], a[mt][1], a[mt][2], a[mt][3],
                         b[nt][0], b[nt][1]);
        }
        __syncthreads();
    }

    const float NEG = -CUDART_INF_F;
#pragma unroll
    for (int mt = 0; mt < 4; mt++) {
#pragma unroll
        for (int rr = 0; rr < 2; rr++) {
            int m = row0 + wm + mt * 16 + g + rr * 8;
#pragma unroll
            for (int nt = 0; nt < 4; nt++) {
                int n = col0 + wn + nt * 8 + 2 * tig;
                float v0 = acc[mt][nt][rr * 2 + 0] * 0.125f;
                float v1 = acc[mt][nt][rr * 2 + 1] * 0.125f;
                if (causal) {
                    if (n > m)     v0 = NEG;
                    if (n + 1 > m) v1 = NEG;
                }
                *reinterpret_cast<float2*>(out + (size_t)m * S + n) =
                    make_float2(v0, v1);
            }
        }
    }
}

// ---------------------------------------------------------------------------
// Row softmax. One block per row. Causal: only loads cols <= row (rest -inf),
// but writes the full row (zeros in the masked region).
// ---------------------------------------------------------------------------
__global__ __launch_bounds__(256) void softmax_kernel(
    float* __restrict__ attn, const int* __restrict__ causal_p)
{
    const size_t row = blockIdx.x;
    const int r_in_s = (int)(row % S);          // row index within a head
    const int causal = *causal_p;
    float* p = attn + row * S;
    const int t = threadIdx.x;

    float x[8];
#pragma unroll
    for (int i = 0; i < 8; i++) {
        int idx = t + 256 * i;
        x[i] = (!causal || idx <= r_in_s) ? p[idx] : -CUDART_INF_F;
    }

    float m = x[0];
#pragma unroll
    for (int i = 1; i < 8; i++) m = fmaxf(m, x[i]);
#pragma unroll
    for (int o = 16; o > 0; o >>= 1)
        m = fmaxf(m, __shfl_xor_sync(0xffffffffu, m, o));

    __shared__ float red[8];
    if ((t & 31) == 0) red[t >> 5] = m;
    __syncthreads();
    float bm = red[0];
#pragma unroll
    for (int i = 1; i < 8; i++) bm = fmaxf(bm, red[i]);

    float ssum = 0.f;
#pragma unroll
    for (int i = 0; i < 8; i++) { x[i] = __expf(x[i] - bm); ssum += x[i]; }
#pragma unroll
    for (int o = 16; o > 0; o >>= 1)
        ssum += __shfl_xor_sync(0xffffffffu, ssum, o);
    __syncthreads();
    if ((t & 31) == 0) red[t >> 5] = ssum;
    __syncthreads();
    float tot = 0.f;
#pragma unroll
    for (int i = 0; i < 8; i++) tot += red[i];

    float inv = 1.0f / tot;
#pragma unroll
    for (int i = 0; i < 8; i++) p[t + 256 * i] = x[i] * inv;
}

// ---------------------------------------------------------------------------
// Context: per (b,h): ctx[i,d] = sum_j attn[i,j] * v[j,d]  (tf32)
// Block 128x64, 256 threads = 8 warps (4m x 2n), warp tile 32x32.
// Causal: j-loop stops at row0+128 (attn is exactly 0 beyond).
// ---------------------------------------------------------------------------
__global__ __launch_bounds__(256) void context_tf32(
    const float* __restrict__ attn, const float* __restrict__ Vp,
    float* __restrict__ ctx, const int* __restrict__ causal_p)
{
    const int z    = blockIdx.z;
    const int row0 = blockIdx.y * 128;
    const int causal = *causal_p;
    const float* Aa = attn + (size_t)z * S * S;
    const float* Vv = Vp + (size_t)z * S * HD;

    __shared__ uint32_t As[16][ASTR];
    __shared__ uint32_t Vs[16][VSTR];

    const int tid  = threadIdx.x;
    const int lane = tid & 31, wid = tid >> 5;
    const int wm = (wid >> 1) * 32, wn = (wid & 1) * 32;
    const int g = lane >> 2, tig = lane & 3;
    const int lr = tid >> 2, lk = (tid & 3) << 2;
    const int vr = tid >> 4, vc = (tid & 15) << 2;

    float acc[2][4][4] = {};
    const int jend = causal ? (row0 + 128) : S;

    for (int j0 = 0; j0 < jend; j0 += 16) {
#pragma unroll
        for (int hh = 0; hh < 2; hh++) {
            int r = lr + hh * 64;
            float4 va = *reinterpret_cast<const float4*>(
                Aa + (size_t)(row0 + r) * S + j0 + lk);
            As[lk + 0][r] = tf32_of(va.x); As[lk + 1][r] = tf32_of(va.y);
            As[lk + 2][r] = tf32_of(va.z); As[lk + 3][r] = tf32_of(va.w);
        }
        {
            float4 vv = *reinterpret_cast<const float4*>(
                Vv + (size_t)(j0 + vr) * HD + vc);
            Vs[vr][vc + 0] = tf32_of(vv.x); Vs[vr][vc + 1] = tf32_of(vv.y);
            Vs[vr][vc + 2] = tf32_of(vv.z); Vs[vr][vc + 3] = tf32_of(vv.w);
        }
        __syncthreads();
#pragma unroll
        for (int kk = 0; kk < 16; kk += 8) {
            uint32_t a[2][4], b[4][2];
#pragma unroll
            for (int mt = 0; mt < 2; mt++) {
                int m = wm + mt * 16 + g;
                a[mt][0] = As[kk + tig][m];     a[mt][1] = As[kk + tig][m + 8];
                a[mt][2] = As[kk + tig + 4][m]; a[mt][3] = As[kk + tig + 4][m + 8];
            }
#pragma unroll
            for (int nt = 0; nt < 4; nt++) {
                int n = wn + nt * 8 + g;
                b[nt][0] = Vs[kk + tig][n];     b[nt][1] = Vs[kk + tig + 4][n];
            }
#pragma unroll
            for (int mt = 0; mt < 2; mt++)
#pragma unroll
                for (int nt = 0; nt < 4; nt++)
                    mma8(acc[mt][nt], a[mt][0], a[mt][1], a[mt][2], a[mt][3],
                         b[nt][0], b[nt][1]);
        }
        __syncthreads();
    }

    const int bb = z / NH, hh2 = z % NH;
#pragma unroll
    for (int mt = 0; mt < 2; mt++) {
#pragma unroll
        for (int rr = 0; rr < 2; rr++) {
            int m = row0 + wm + mt * 16 + g + rr * 8;
#pragma unroll
            for (int nt = 0; nt < 4; nt++) {
                int n = wn + nt * 8 + 2 * tig;
                float v0 = acc[mt][nt][rr * 2 + 0];
                float v1 = acc[mt][nt][rr * 2 + 1];
                *reinterpret_cast<float2*>(
                    ctx + ((size_t)bb * S + m) * H + hh2 * HD + n) =
                    make_float2(v0, v1);
            }
        }
    }
}

// ---------------------------------------------------------------------------
// Launch
// ---------------------------------------------------------------------------
extern "C" void kernel_launch(void* const* d_in, const int* in_sizes, int n_in,
                              void* d_out, int out_size)
{
    const float* query = (const float*)d_in[0];
    const float* key_  = (const float*)d_in[1];
    const float* value = (const float*)d_in[2];
    const float* Wq = (const float*)d_in[3];
    const float* bq = (const float*)d_in[4];
    const float* Wk = (const float*)d_in[5];
    const float* bk = (const float*)d_in[6];
    const float* Wv = (const float*)d_in[7];
    const float* bv = (const float*)d_in[8];
    const float* Wo = (const float*)d_in[9];
    const float* bo = (const float*)d_in[10];
    const int* causal = (const int*)d_in[11];

    float *qp, *kp, *vp, *cp, *afb;
    cudaGetSymbolAddress((void**)&qp, g_q);
    cudaGetSymbolAddress((void**)&kp, g_k);
    cudaGetSymbolAddress((void**)&vp, g_v);
    cudaGetSymbolAddress((void**)&cp, g_ctx);
    cudaGetSymbolAddress((void**)&afb, g_attn_fb);

    float* out = (float*)d_out;
    float* attn = ((size_t)out_size >= OUT_ELEMS + ATTN_ELEMS) ? (out + OUT_ELEMS)
                                                               : afb;

    dim3 gproj(H / 128, MROWS / 128);                 // (8, 64)
    gemm_tf32<1><<<gproj, 256>>>(query, Wq, bq, qp, MROWS, H, H);
    gemm_tf32<1><<<gproj, 256>>>(key_,  Wk, bk, kp, MROWS, H, H);
    gemm_tf32<1><<<gproj, 256>>>(value, Wv, bv, vp, MROWS, H, H);

    dim3 gsc(S / 128, S / 128, B * NH);               // (16, 16, 64)
    scores_tf32<<<gsc, 256>>>(qp, kp, attn, causal);

    softmax_kernel<<<B * NH * S, 256>>>(attn, causal);

    dim3 gctx(1, S / 128, B * NH);                    // (1, 16, 64)
    context_tf32<<<gctx, 256>>>(attn, vp, cp, causal);

    gemm_tf32<0><<<gproj, 256>>>(cp, Wo, bo, out, MROWS, H, H);
}